// round 16
// baseline (speedup 1.0000x reference)
#include <cuda_runtime.h>
#include <math_constants.h>
#include <cstdint>

// Tropical (max-plus) depthwise 5x5 conv, stride=1, pad=2, dil=1.
// x: (8,32,224,224) f32, kernel: (32,1,5,5) f32, out same shape as x.
// out[b,c,y,x] = max_{i,j} x[b,c, y+i-2, x+j-2] + kernel[c,0,4-i,4-j]
//
// R16: R15 (no-smem sliding ring) stalled on raw LDG->use (L2 ~260cyc,
// issue 61.7%). Depth-1 software pipeline: each step loads row r+1 into
// next-regs BEFORE computing row r from current regs -> consumer distance
// ~170 fp inst. Uniform rolled 5-step body keeps code ~20KB.

static constexpr int Hdim = 224;
static constexpr int Wdim = 224;
static constexpr int NCG  = 56;    // 4-wide column groups per row

__constant__ float cw[32 * 25];    // raw (unflipped) kernel from d_in[1]

// flipped weight (i,j): kernel[c,0,4-i,4-j] = cw[base + 24 - (5i+j)]
#define WGT(i, j) cw[wbase + (24 - ((i) * 5 + (j)))]

// One pipelined step. K = r mod 5 (compile-time), RR = runtime row index r.
// 1) prefetch row RR+1 (predicated on gy validity), 2) compute row RR from
// current regs, 3) store output row ys+RR-4 when RR>=4, 4) rotate regs.
#define STEP(K, RR, LOADNEXT)                                               \
  {                                                                         \
    float2 nl; float4 nm; float2 nh;                                        \
    if (LOADNEXT) {                                                         \
      const int gy = ys - 1 + (RR);               /* row RR+1 */            \
      const bool ok = (unsigned)gy < (unsigned)Hdim;                        \
      const float* rp = bx + ((RR) + 1) * Wdim;                             \
      nl = (ok && okL) ? *(const float2*)(rp - 2) : make_float2(NI, NI);    \
      nm = ok ? *(const float4*)(rp) : make_float4(NI, NI, NI, NI);         \
      nh = (ok && okR) ? *(const float2*)(rp + 4) : make_float2(NI, NI);    \
    } else {                                                                \
      nl = make_float2(NI, NI); nm = make_float4(NI, NI, NI, NI);           \
      nh = make_float2(NI, NI);                                             \
    }                                                                       \
    const float xw[8] = {cl.x, cl.y, cm.x, cm.y, cm.z, cm.w, ch.x, ch.y};   \
    _Pragma("unroll")                                                       \
    for (int i = 0; i < 5; i++) {                                           \
      const int s = ((K) - i + 5) % 5;                                      \
      _Pragma("unroll")                                                     \
      for (int t = 0; t < 4; t++) {                                         \
        float h = xw[t] + WGT(i, 0);                                        \
        h = fmaxf(h, xw[t + 1] + WGT(i, 1));                                \
        h = fmaxf(h, xw[t + 2] + WGT(i, 2));                                \
        h = fmaxf(h, xw[t + 3] + WGT(i, 3));                                \
        h = fmaxf(h, xw[t + 4] + WGT(i, 4));                                \
        if (i == 0) acc[s][t] = h;                                          \
        else        acc[s][t] = fmaxf(acc[s][t], h);                        \
      }                                                                     \
    }                                                                       \
    if ((RR) >= 4) {                                                        \
      const int ss = ((K) + 1) % 5;                                         \
      *(float4*)(bo + (RR) * Wdim) =                                        \
          make_float4(acc[ss][0], acc[ss][1], acc[ss][2], acc[ss][3]);      \
    }                                                                       \
    cl = nl; cm = nm; ch = nh;                                              \
  }

__global__ __launch_bounds__(224, 4)
void tropical_conv_kernel(const float* __restrict__ x,
                          float* __restrict__ out) {
    const int cg    = threadIdx.x;                       // 0..55
    const int strip = blockIdx.y * 4 + threadIdx.y;      // 0..7
    const int bc    = blockIdx.z;                        // b*32 + c
    const int wbase = (bc & 31) * 25;                    // block-uniform -> UR
    const int ys    = strip * 28;
    const int x0    = 4 * cg;

    const float* __restrict__ bx =
        x + (size_t)bc * (Hdim * Wdim) + (ys - 2) * Wdim + x0;
    float* __restrict__ bo =
        out + (size_t)bc * (Hdim * Wdim) + (ys - 4) * Wdim + x0;

    const bool okL = (cg > 0);
    const bool okR = (cg < NCG - 1);
    const float NI = -CUDART_INF_F;

    float acc[5][4];
    #pragma unroll
    for (int s = 0; s < 5; s++)
        #pragma unroll
        for (int t = 0; t < 4; t++) acc[s][t] = NI;

    // Prime the pipeline: load row 0 (gy = ys-2; invalid only for strip 0).
    float2 cl; float4 cm; float2 ch;
    {
        const bool ok = (unsigned)(ys - 2) < (unsigned)Hdim;
        cl = (ok && okL) ? *(const float2*)(bx - 2) : make_float2(NI, NI);
        cm = ok ? *(const float4*)(bx) : make_float4(NI, NI, NI, NI);
        ch = (ok && okR) ? *(const float2*)(bx + 4) : make_float2(NI, NI);
    }

    // Rows 0..29 in six rolled 5-step bodies (K pattern repeats mod 5).
    // All gy / store conditions are handled by the in-step predicates.
    #pragma unroll 1
    for (int rb = 0; rb < 30; rb += 5) {
        STEP(0, rb + 0, true)
        STEP(1, rb + 1, true)
        STEP(2, rb + 2, true)
        STEP(3, rb + 3, true)
        STEP(4, rb + 4, true)
    }

    // Tail: rows 30 (loads row 31) and 31 (no load).
    STEP(0, 30, true)
    STEP(1, 31, false)
}

extern "C" void kernel_launch(void* const* d_in, const int* in_sizes, int n_in,
                              void* d_out, int out_size) {
    const float* x = (const float*)d_in[0];
    float* out = (float*)d_out;

    // Stage weights into constant memory (D2D async copy, graph-capturable).
    cudaMemcpyToSymbolAsync(cw, d_in[1], 32 * 25 * sizeof(float), 0,
                            cudaMemcpyDeviceToDevice, 0);

    dim3 block(NCG, 4, 1);          // 224 threads, one bc per block
    dim3 grid(1, 2, 8 * 32);        // 2 strip-quads, 256 bc images
    tropical_conv_kernel<<<grid, block>>>(x, out);
}